// round 1
// baseline (speedup 1.0000x reference)
#include <cuda_runtime.h>
#include <math.h>

#define N_NODES 50000
#define N_EDGES 800000

// ---------------- scratch (static device globals; no runtime alloc) --------
__device__ int   g_counts[N_NODES];
__device__ int   g_offsets[N_NODES + 1];
__device__ int   g_cursor[N_NODES];
__device__ int   g_csr[N_EDGES];
__device__ float g_h64[(size_t)N_NODES * 64];
__device__ float g_xf [(size_t)N_NODES * 256];
__device__ float g_hA [(size_t)N_NODES * 256];
__device__ float g_hB [(size_t)N_NODES * 256];
__device__ float g_esrc[N_NODES * 4];
__device__ float g_edst[N_NODES * 4];
__device__ float g_pool[64];

// ---------------- CSR build ------------------------------------------------
__global__ void zero_kernel() {
    int i = blockIdx.x * blockDim.x + threadIdx.x;
    if (i < N_NODES) g_counts[i] = 0;
    if (i < 64) g_pool[i] = 0.f;
}

__global__ void hist_kernel(const int* __restrict__ dst) {
    int i = blockIdx.x * blockDim.x + threadIdx.x;
    if (i < N_EDGES) atomicAdd(&g_counts[dst[i]], 1);
}

__global__ void scan_kernel() {
    __shared__ int ssum[1024];
    int t = threadIdx.x;
    const int CH = (N_NODES + 1023) / 1024;
    int base = t * CH;
    int s = 0;
    for (int c = 0; c < CH; c++) {
        int idx = base + c;
        if (idx < N_NODES) s += g_counts[idx];
    }
    ssum[t] = s;
    __syncthreads();
    for (int off = 1; off < 1024; off <<= 1) {
        int v = (t >= off) ? ssum[t - off] : 0;
        __syncthreads();
        ssum[t] += v;
        __syncthreads();
    }
    int run = (t == 0) ? 0 : ssum[t - 1];
    for (int c = 0; c < CH; c++) {
        int idx = base + c;
        if (idx < N_NODES) {
            g_offsets[idx] = run;
            g_cursor[idx]  = run;
            run += g_counts[idx];
        }
    }
    if (t == 1023) g_offsets[N_NODES] = ssum[1023];
}

__global__ void scatter_kernel(const int* __restrict__ src, const int* __restrict__ dst) {
    int i = blockIdx.x * blockDim.x + threadIdx.x;
    if (i < N_EDGES) {
        int p = atomicAdd(&g_cursor[dst[i]], 1);
        g_csr[p] = src[i];
    }
}

// ---------------- SGEMM (row-major A[MxK] * B[KxN] = C[MxN]) ---------------
// mode 0: plain store; mode 1: +bias, elu
__global__ void sgemm_kernel(const float* __restrict__ A, const float* __restrict__ B,
                             const float* __restrict__ bias, float* __restrict__ C,
                             int M, int N, int K, int mode) {
    const int BM = 64, BN = 64, BK = 16;
    __shared__ float As[BK][BM + 1];
    __shared__ float Bs[BK][BN + 1];
    int tx = threadIdx.x;                 // 0..255
    int block_m = blockIdx.y * BM;
    int block_n = blockIdx.x * BN;
    int tr = tx >> 4, tc = tx & 15;       // 16x16 thread tile, 4x4 per thread

    float acc[4][4];
#pragma unroll
    for (int i = 0; i < 4; i++)
#pragma unroll
        for (int j = 0; j < 4; j++) acc[i][j] = 0.f;

    for (int k0 = 0; k0 < K; k0 += BK) {
        // A tile: 64 rows x 16 k; each thread loads 4 consecutive k
        int ar = tx >> 2;
        int ak = (tx & 3) * 4;
        int gm = block_m + ar;
        float4 av = make_float4(0.f, 0.f, 0.f, 0.f);
        if (gm < M) av = *(const float4*)&A[(size_t)gm * K + k0 + ak];
        As[ak + 0][ar] = av.x; As[ak + 1][ar] = av.y;
        As[ak + 2][ar] = av.z; As[ak + 3][ar] = av.w;
        // B tile: 16 k x 64 cols
        int br = tx >> 4;
        int bc = (tx & 15) * 4;
        float4 bv = *(const float4*)&B[(size_t)(k0 + br) * N + block_n + bc];
        Bs[br][bc + 0] = bv.x; Bs[br][bc + 1] = bv.y;
        Bs[br][bc + 2] = bv.z; Bs[br][bc + 3] = bv.w;
        __syncthreads();
#pragma unroll
        for (int kk = 0; kk < BK; kk++) {
            float a[4], b[4];
#pragma unroll
            for (int i = 0; i < 4; i++) a[i] = As[kk][tr * 4 + i];
#pragma unroll
            for (int j = 0; j < 4; j++) b[j] = Bs[kk][tc * 4 + j];
#pragma unroll
            for (int i = 0; i < 4; i++)
#pragma unroll
                for (int j = 0; j < 4; j++) acc[i][j] += a[i] * b[j];
        }
        __syncthreads();
    }
#pragma unroll
    for (int i = 0; i < 4; i++) {
        int m = block_m + tr * 4 + i;
        if (m >= M) continue;
#pragma unroll
        for (int j = 0; j < 4; j++) {
            int n = block_n + tc * 4 + j;
            float v = acc[i][j];
            if (mode == 1) {
                v += bias[n];
                v = v > 0.f ? v : expm1f(v);
            }
            C[(size_t)m * N + n] = v;
        }
    }
}

// ---------------- attention logits: e_src / e_dst --------------------------
template <int H, int D>
__global__ void compute_e_kernel(const float* __restrict__ xf,
                                 const float* __restrict__ a_s,
                                 const float* __restrict__ a_d) {
    constexpr int F = H * D;
    constexpr int FP = F / 32;
    int gw = (blockIdx.x * blockDim.x + threadIdx.x) >> 5;
    int lane = threadIdx.x & 31;
    if (gw >= N_NODES) return;
    const float* xr = xf + (size_t)gw * F;
    float ps = 0.f, pd = 0.f;
#pragma unroll
    for (int q = 0; q < FP; q++) {
        int f = lane * FP + q;
        float v = xr[f];
        ps += v * a_s[f];
        pd += v * a_d[f];
    }
    constexpr int G = 32 / H;  // lanes per head
#pragma unroll
    for (int off = G >> 1; off; off >>= 1) {
        ps += __shfl_down_sync(0xffffffffu, ps, off);
        pd += __shfl_down_sync(0xffffffffu, pd, off);
    }
    if ((lane & (G - 1)) == 0) {
        int h = lane / G;
        g_esrc[gw * H + h] = ps;
        g_edst[gw * H + h] = pd;
    }
}

// ---------------- GAT aggregation: warp per destination node ---------------
template <int H, int D>
__global__ void gat_agg_kernel(const float* __restrict__ xf,
                               const float* __restrict__ bias,
                               float* __restrict__ out) {
    constexpr int F = H * D;
    constexpr int FP = F / 32;
    int gw = (blockIdx.x * blockDim.x + threadIdx.x) >> 5;
    int lane = threadIdx.x & 31;
    if (gw >= N_NODES) return;
    const int i = gw;
    const int beg = g_offsets[i], end = g_offsets[i + 1];

    float edst_i[H], eself[H], m[H];
#pragma unroll
    for (int h = 0; h < H; h++) {
        edst_i[h] = g_edst[i * H + h];
        float v = g_esrc[i * H + h] + edst_i[h];
        v = v > 0.f ? v : 0.2f * v;
        eself[h] = v;
        m[h] = v;  // self-loop participates in max
    }
    // pass 1: segment max over incoming edges (scalar logits only)
    for (int k = beg + lane; k < end; k += 32) {
        int s = g_csr[k];
#pragma unroll
        for (int h = 0; h < H; h++) {
            float v = g_esrc[s * H + h] + edst_i[h];
            v = v > 0.f ? v : 0.2f * v;
            m[h] = fmaxf(m[h], v);
        }
    }
#pragma unroll
    for (int h = 0; h < H; h++)
#pragma unroll
        for (int off = 16; off; off >>= 1)
            m[h] = fmaxf(m[h], __shfl_xor_sync(0xffffffffu, m[h], off));

    // pass 2: exp-weights, running sum, warp-cooperative feature gather
    float acc[FP];
#pragma unroll
    for (int q = 0; q < FP; q++) acc[q] = 0.f;
    float ssum[H];
#pragma unroll
    for (int h = 0; h < H; h++) ssum[h] = 0.f;
    const int myh = (lane * FP) / D;

    for (int base = beg; base < end; base += 32) {
        int k = base + lane;
        int cnt = min(32, end - base);
        int s = 0;
        float w[H];
#pragma unroll
        for (int h = 0; h < H; h++) w[h] = 0.f;
        if (k < end) {
            s = g_csr[k];
#pragma unroll
            for (int h = 0; h < H; h++) {
                float v = g_esrc[s * H + h] + edst_i[h];
                v = v > 0.f ? v : 0.2f * v;
                float ww = __expf(v - m[h]);
                w[h] = ww;
                ssum[h] += ww;
            }
        }
        for (int j = 0; j < cnt; j++) {
            int sj = __shfl_sync(0xffffffffu, s, j);
            float wh;
            if constexpr (H == 4) {
                float w0 = __shfl_sync(0xffffffffu, w[0], j);
                float w1 = __shfl_sync(0xffffffffu, w[1], j);
                float w2 = __shfl_sync(0xffffffffu, w[2], j);
                float w3 = __shfl_sync(0xffffffffu, w[3], j);
                wh = (myh == 0) ? w0 : (myh == 1) ? w1 : (myh == 2) ? w2 : w3;
            } else {
                wh = __shfl_sync(0xffffffffu, w[0], j);
            }
            const float* xr = xf + (size_t)sj * F;
            if constexpr (FP == 8) {
                float4 v0 = ((const float4*)xr)[lane * 2];
                float4 v1 = ((const float4*)xr)[lane * 2 + 1];
                acc[0] += wh * v0.x; acc[1] += wh * v0.y;
                acc[2] += wh * v0.z; acc[3] += wh * v0.w;
                acc[4] += wh * v1.x; acc[5] += wh * v1.y;
                acc[6] += wh * v1.z; acc[7] += wh * v1.w;
            } else {
                float2 v = ((const float2*)xr)[lane];
                acc[0] += wh * v.x; acc[1] += wh * v.y;
            }
        }
    }
    // total exp-sum across the warp, then fold in self-loop (uniform on all lanes)
#pragma unroll
    for (int h = 0; h < H; h++)
#pragma unroll
        for (int off = 16; off; off >>= 1)
            ssum[h] += __shfl_xor_sync(0xffffffffu, ssum[h], off);
    float wself[H];
#pragma unroll
    for (int h = 0; h < H; h++) {
        wself[h] = __expf(eself[h] - m[h]);
        ssum[h] += wself[h];
    }
    {
        float wh;
        if constexpr (H == 4)
            wh = (myh == 0) ? wself[0] : (myh == 1) ? wself[1] : (myh == 2) ? wself[2] : wself[3];
        else
            wh = wself[0];
        const float* xr = xf + (size_t)i * F;
        if constexpr (FP == 8) {
            float4 v0 = ((const float4*)xr)[lane * 2];
            float4 v1 = ((const float4*)xr)[lane * 2 + 1];
            acc[0] += wh * v0.x; acc[1] += wh * v0.y;
            acc[2] += wh * v0.z; acc[3] += wh * v0.w;
            acc[4] += wh * v1.x; acc[5] += wh * v1.y;
            acc[6] += wh * v1.z; acc[7] += wh * v1.w;
        } else {
            float2 v = ((const float2*)xr)[lane];
            acc[0] += wh * v.x; acc[1] += wh * v.y;
        }
    }
    float denom;
    if constexpr (H == 4)
        denom = (myh == 0) ? ssum[0] : (myh == 1) ? ssum[1] : (myh == 2) ? ssum[2] : ssum[3];
    else
        denom = ssum[0];
    float inv = 1.f / denom;
#pragma unroll
    for (int q = 0; q < FP; q++) {
        int f = lane * FP + q;
        float v = acc[q] * inv + bias[f];
        v = v > 0.f ? v : expm1f(v);   // elu applied after every GAT layer
        out[(size_t)i * F + f] = v;
    }
}

// ---------------- global mean pool + output projection ---------------------
__global__ void pool_kernel(const float* __restrict__ h) {
    __shared__ float sacc[64];
    int t = threadIdx.x;
    if (t < 64) sacc[t] = 0.f;
    __syncthreads();
    int col = t & 63;
    int rpb = blockDim.x >> 6;  // rows per block pass
    float a = 0.f;
    for (int r = blockIdx.x * rpb + (t >> 6); r < N_NODES; r += gridDim.x * rpb)
        a += h[(size_t)r * 64 + col];
    atomicAdd(&sacc[col], a);
    __syncthreads();
    if (t < 64) atomicAdd(&g_pool[t], sacc[t]);
}

__global__ void final_kernel(const float* __restrict__ w_out,
                             const float* __restrict__ b_out,
                             float* __restrict__ out) {
    int j = threadIdx.x;  // 0..127
    float s = b_out[j];
    const float invn = 1.f / (float)N_NODES;
    for (int k = 0; k < 64; k++)
        s += g_pool[k] * invn * w_out[k * 128 + j];
    out[j] = s;
}

// ---------------- launcher -------------------------------------------------
extern "C" void kernel_launch(void* const* d_in, const int* in_sizes, int n_in,
                              void* d_out, int out_size) {
    const float* x     = (const float*)d_in[0];
    const int*   ei    = (const int*)d_in[1];
    const int*   src   = ei;
    const int*   dst   = ei + N_EDGES;
    const float* w_in  = (const float*)d_in[2];
    const float* b_in  = (const float*)d_in[3];
    const float* W0    = (const float*)d_in[4];
    const float* as0   = (const float*)d_in[5];
    const float* ad0   = (const float*)d_in[6];
    const float* bb0   = (const float*)d_in[7];
    const float* W1    = (const float*)d_in[8];
    const float* as1   = (const float*)d_in[9];
    const float* ad1   = (const float*)d_in[10];
    const float* bb1   = (const float*)d_in[11];
    const float* W2    = (const float*)d_in[12];
    const float* as2   = (const float*)d_in[13];
    const float* ad2   = (const float*)d_in[14];
    const float* bb2   = (const float*)d_in[15];
    const float* w_out = (const float*)d_in[16];
    const float* b_out = (const float*)d_in[17];
    float* out = (float*)d_out;

    void *p_h64, *p_xf, *p_hA, *p_hB;
    cudaGetSymbolAddress(&p_h64, g_h64);
    cudaGetSymbolAddress(&p_xf,  g_xf);
    cudaGetSymbolAddress(&p_hA,  g_hA);
    cudaGetSymbolAddress(&p_hB,  g_hB);
    float* h64 = (float*)p_h64;
    float* xf  = (float*)p_xf;
    float* hA  = (float*)p_hA;
    float* hB  = (float*)p_hB;

    const int EB = (N_EDGES + 255) / 256;
    const int NB = (N_NODES + 255) / 256;
    const int MY = (N_NODES + 63) / 64;     // 782
    const int WARPB = N_NODES / 8;          // 6250 blocks of 8 warps

    // CSR build (per-launch; deterministic workload)
    zero_kernel<<<NB, 256>>>();
    hist_kernel<<<EB, 256>>>(dst);
    scan_kernel<<<1, 1024>>>();
    scatter_kernel<<<EB, 256>>>(src, dst);

    // input MLP: h64 = elu(x @ w_in + b_in)
    sgemm_kernel<<<dim3(1, MY), 256>>>(x, w_in, b_in, h64, N_NODES, 64, 256, 1);

    // GAT layer 0 (H=4, D=64, concat)
    sgemm_kernel<<<dim3(4, MY), 256>>>(h64, W0, nullptr, xf, N_NODES, 256, 64, 0);
    compute_e_kernel<4, 64><<<WARPB, 256>>>(xf, as0, ad0);
    gat_agg_kernel<4, 64><<<WARPB, 256>>>(xf, bb0, hA);

    // GAT layer 1 (H=4, D=64, concat)
    sgemm_kernel<<<dim3(4, MY), 256>>>(hA, W1, nullptr, xf, N_NODES, 256, 256, 0);
    compute_e_kernel<4, 64><<<WARPB, 256>>>(xf, as1, ad1);
    gat_agg_kernel<4, 64><<<WARPB, 256>>>(xf, bb1, hB);

    // GAT layer 2 (H=1, D=64, mean over heads == identity)
    sgemm_kernel<<<dim3(1, MY), 256>>>(hB, W2, nullptr, xf, N_NODES, 64, 256, 0);
    compute_e_kernel<1, 64><<<WARPB, 256>>>(xf, as2, ad2);
    gat_agg_kernel<1, 64><<<WARPB, 256>>>(xf, bb2, h64);

    // global mean pool + out projection
    pool_kernel<<<256, 256>>>(h64);
    final_kernel<<<1, 128>>>(w_out, b_out, out);
}

// round 2
// speedup vs baseline: 1.2068x; 1.2068x over previous
#include <cuda_runtime.h>
#include <math.h>

#define N_NODES 50000
#define N_EDGES 800000

// ---------------- scratch (static device globals; no runtime alloc) --------
__device__ int   g_counts[N_NODES];
__device__ int   g_offsets[N_NODES + 1];
__device__ int   g_cursor[N_NODES];
__device__ int   g_csr[N_EDGES];
__device__ float g_h64[(size_t)N_NODES * 64];
__device__ float g_xf [(size_t)N_NODES * 256];
__device__ float g_hA [(size_t)N_NODES * 256];
__device__ float g_hB [(size_t)N_NODES * 256];
__device__ float g_esrc[N_NODES * 4];
__device__ float g_edst[N_NODES * 4];
__device__ float g_pool[64];

// ---------------- CSR build ------------------------------------------------
__global__ void zero_kernel() {
    int i = blockIdx.x * blockDim.x + threadIdx.x;
    if (i < N_NODES) g_counts[i] = 0;
    if (i < 64) g_pool[i] = 0.f;
}

__global__ void hist_kernel(const int* __restrict__ dst) {
    int i = blockIdx.x * blockDim.x + threadIdx.x;
    if (i < N_EDGES) atomicAdd(&g_counts[dst[i]], 1);
}

__global__ void scan_kernel() {
    __shared__ int ssum[1024];
    int t = threadIdx.x;
    const int CH = (N_NODES + 1023) / 1024;
    int base = t * CH;
    int s = 0;
    for (int c = 0; c < CH; c++) {
        int idx = base + c;
        if (idx < N_NODES) s += g_counts[idx];
    }
    ssum[t] = s;
    __syncthreads();
    for (int off = 1; off < 1024; off <<= 1) {
        int v = (t >= off) ? ssum[t - off] : 0;
        __syncthreads();
        ssum[t] += v;
        __syncthreads();
    }
    int run = (t == 0) ? 0 : ssum[t - 1];
    for (int c = 0; c < CH; c++) {
        int idx = base + c;
        if (idx < N_NODES) {
            g_offsets[idx] = run;
            g_cursor[idx]  = run;
            run += g_counts[idx];
        }
    }
    if (t == 1023) g_offsets[N_NODES] = ssum[1023];
}

__global__ void scatter_kernel(const int* __restrict__ src, const int* __restrict__ dst) {
    int i = blockIdx.x * blockDim.x + threadIdx.x;
    if (i < N_EDGES) {
        int p = atomicAdd(&g_cursor[dst[i]], 1);
        g_csr[p] = src[i];
    }
}

// ---------------- SGEMM: 128x64 block tile, 8x4 microtile, reg prefetch ----
// mode 0: plain store; mode 1: +bias, elu
__global__ __launch_bounds__(256) void sgemm_kernel(
        const float* __restrict__ A, const float* __restrict__ B,
        const float* __restrict__ bias, float* __restrict__ C,
        int M, int N, int K, int mode) {
    const int BM = 128, BN = 64, BK = 16;
    __shared__ float As[BK][BM + 4];
    __shared__ float Bs[BK][BN + 4];
    int tx = threadIdx.x;                 // 0..255
    int bm = blockIdx.y * BM;
    int bn = blockIdx.x * BN;
    int tr = tx >> 4, tc = tx & 15;       // 16x16 threads; 8 rows x 4 cols each

    // A-load mapping: 512 float4 per tile; thread loads idx=tx and tx+256
    const int a_r0 = tx >> 2;             // 0..63
    const int a_k  = (tx & 3) * 4;        // 0,4,8,12
    // B-load mapping: 256 float4 per tile
    const int b_r  = tx >> 4;             // 0..15
    const int b_c  = (tx & 15) * 4;       // 0..60

    float acc[8][4];
#pragma unroll
    for (int i = 0; i < 8; i++)
#pragma unroll
        for (int j = 0; j < 4; j++) acc[i][j] = 0.f;

    const float4 z4 = make_float4(0.f, 0.f, 0.f, 0.f);
    float4 pa0, pa1, pb;

    // prefetch tile 0
    {
        int gm0 = bm + a_r0;
        int gm1 = gm0 + 64;
        pa0 = (gm0 < M) ? *(const float4*)&A[(size_t)gm0 * K + a_k] : z4;
        pa1 = (gm1 < M) ? *(const float4*)&A[(size_t)gm1 * K + a_k] : z4;
        pb  = *(const float4*)&B[(size_t)b_r * N + bn + b_c];
    }

    for (int k0 = 0; k0 < K; k0 += BK) {
        // commit prefetched tile to smem
        As[a_k + 0][a_r0] = pa0.x; As[a_k + 1][a_r0] = pa0.y;
        As[a_k + 2][a_r0] = pa0.z; As[a_k + 3][a_r0] = pa0.w;
        As[a_k + 0][a_r0 + 64] = pa1.x; As[a_k + 1][a_r0 + 64] = pa1.y;
        As[a_k + 2][a_r0 + 64] = pa1.z; As[a_k + 3][a_r0 + 64] = pa1.w;
        Bs[b_r][b_c + 0] = pb.x; Bs[b_r][b_c + 1] = pb.y;
        Bs[b_r][b_c + 2] = pb.z; Bs[b_r][b_c + 3] = pb.w;
        __syncthreads();

        // prefetch next tile into registers (overlaps with compute)
        if (k0 + BK < K) {
            int kk = k0 + BK;
            int gm0 = bm + a_r0;
            int gm1 = gm0 + 64;
            pa0 = (gm0 < M) ? *(const float4*)&A[(size_t)gm0 * K + kk + a_k] : z4;
            pa1 = (gm1 < M) ? *(const float4*)&A[(size_t)gm1 * K + kk + a_k] : z4;
            pb  = *(const float4*)&B[(size_t)(kk + b_r) * N + bn + b_c];
        }

#pragma unroll
        for (int kk = 0; kk < BK; kk++) {
            float4 a0 = *(const float4*)&As[kk][tr * 8];
            float4 a1 = *(const float4*)&As[kk][tr * 8 + 4];
            float4 b  = *(const float4*)&Bs[kk][tc * 4];
            float ar[8] = {a0.x, a0.y, a0.z, a0.w, a1.x, a1.y, a1.z, a1.w};
            float br[4] = {b.x, b.y, b.z, b.w};
#pragma unroll
            for (int i = 0; i < 8; i++)
#pragma unroll
                for (int j = 0; j < 4; j++) acc[i][j] += ar[i] * br[j];
        }
        __syncthreads();
    }

#pragma unroll
    for (int i = 0; i < 8; i++) {
        int m = bm + tr * 8 + i;
        if (m >= M) continue;
#pragma unroll
        for (int j = 0; j < 4; j++) {
            int n = bn + tc * 4 + j;
            float v = acc[i][j];
            if (mode == 1) {
                v += bias[n];
                v = v > 0.f ? v : expm1f(v);
            }
            C[(size_t)m * N + n] = v;
        }
    }
}

// ---------------- attention logits: e_src / e_dst --------------------------
template <int H, int D>
__global__ void compute_e_kernel(const float* __restrict__ xf,
                                 const float* __restrict__ a_s,
                                 const float* __restrict__ a_d) {
    constexpr int F = H * D;
    constexpr int FP = F / 32;
    int gw = (blockIdx.x * blockDim.x + threadIdx.x) >> 5;
    int lane = threadIdx.x & 31;
    if (gw >= N_NODES) return;
    const float* xr = xf + (size_t)gw * F;
    float ps = 0.f, pd = 0.f;
#pragma unroll
    for (int q = 0; q < FP; q++) {
        int f = lane * FP + q;
        float v = xr[f];
        ps += v * a_s[f];
        pd += v * a_d[f];
    }
    constexpr int G = 32 / H;  // lanes per head
#pragma unroll
    for (int off = G >> 1; off; off >>= 1) {
        ps += __shfl_down_sync(0xffffffffu, ps, off);
        pd += __shfl_down_sync(0xffffffffu, pd, off);
    }
    if ((lane & (G - 1)) == 0) {
        int h = lane / G;
        g_esrc[gw * H + h] = ps;
        g_edst[gw * H + h] = pd;
    }
}

// ---------------- GAT aggregation: warp per destination node ---------------
template <int H, int D>
__global__ void gat_agg_kernel(const float* __restrict__ xf,
                               const float* __restrict__ bias,
                               float* __restrict__ out) {
    constexpr int F = H * D;
    constexpr int FP = F / 32;
    int gw = (blockIdx.x * blockDim.x + threadIdx.x) >> 5;
    int lane = threadIdx.x & 31;
    if (gw >= N_NODES) return;
    const int i = gw;
    const int beg = g_offsets[i], end = g_offsets[i + 1];

    float edst_i[H], eself[H], m[H];
#pragma unroll
    for (int h = 0; h < H; h++) {
        edst_i[h] = g_edst[i * H + h];
        float v = g_esrc[i * H + h] + edst_i[h];
        v = v > 0.f ? v : 0.2f * v;
        eself[h] = v;
        m[h] = v;  // self-loop participates in max
    }
    // pass 1: segment max over incoming edges (scalar logits only)
    for (int k = beg + lane; k < end; k += 32) {
        int s = g_csr[k];
#pragma unroll
        for (int h = 0; h < H; h++) {
            float v = g_esrc[s * H + h] + edst_i[h];
            v = v > 0.f ? v : 0.2f * v;
            m[h] = fmaxf(m[h], v);
        }
    }
#pragma unroll
    for (int h = 0; h < H; h++)
#pragma unroll
        for (int off = 16; off; off >>= 1)
            m[h] = fmaxf(m[h], __shfl_xor_sync(0xffffffffu, m[h], off));

    // pass 2: exp-weights, running sum, warp-cooperative feature gather
    float acc[FP];
#pragma unroll
    for (int q = 0; q < FP; q++) acc[q] = 0.f;
    float ssum[H];
#pragma unroll
    for (int h = 0; h < H; h++) ssum[h] = 0.f;
    const int myh = (lane * FP) / D;

    for (int base = beg; base < end; base += 32) {
        int k = base + lane;
        int cnt = min(32, end - base);
        int s = 0;
        float w[H];
#pragma unroll
        for (int h = 0; h < H; h++) w[h] = 0.f;
        if (k < end) {
            s = g_csr[k];
#pragma unroll
            for (int h = 0; h < H; h++) {
                float v = g_esrc[s * H + h] + edst_i[h];
                v = v > 0.f ? v : 0.2f * v;
                float ww = __expf(v - m[h]);
                w[h] = ww;
                ssum[h] += ww;
            }
        }
        for (int j = 0; j < cnt; j++) {
            int sj = __shfl_sync(0xffffffffu, s, j);
            float wh;
            if constexpr (H == 4) {
                float w0 = __shfl_sync(0xffffffffu, w[0], j);
                float w1 = __shfl_sync(0xffffffffu, w[1], j);
                float w2 = __shfl_sync(0xffffffffu, w[2], j);
                float w3 = __shfl_sync(0xffffffffu, w[3], j);
                wh = (myh == 0) ? w0 : (myh == 1) ? w1 : (myh == 2) ? w2 : w3;
            } else {
                wh = __shfl_sync(0xffffffffu, w[0], j);
            }
            const float* xr = xf + (size_t)sj * F;
            if constexpr (FP == 8) {
                float4 v0 = ((const float4*)xr)[lane * 2];
                float4 v1 = ((const float4*)xr)[lane * 2 + 1];
                acc[0] += wh * v0.x; acc[1] += wh * v0.y;
                acc[2] += wh * v0.z; acc[3] += wh * v0.w;
                acc[4] += wh * v1.x; acc[5] += wh * v1.y;
                acc[6] += wh * v1.z; acc[7] += wh * v1.w;
            } else {
                float2 v = ((const float2*)xr)[lane];
                acc[0] += wh * v.x; acc[1] += wh * v.y;
            }
        }
    }
    // total exp-sum across the warp, then fold in self-loop (uniform on all lanes)
#pragma unroll
    for (int h = 0; h < H; h++)
#pragma unroll
        for (int off = 16; off; off >>= 1)
            ssum[h] += __shfl_xor_sync(0xffffffffu, ssum[h], off);
    float wself[H];
#pragma unroll
    for (int h = 0; h < H; h++) {
        wself[h] = __expf(eself[h] - m[h]);
        ssum[h] += wself[h];
    }
    {
        float wh;
        if constexpr (H == 4)
            wh = (myh == 0) ? wself[0] : (myh == 1) ? wself[1] : (myh == 2) ? wself[2] : wself[3];
        else
            wh = wself[0];
        const float* xr = xf + (size_t)i * F;
        if constexpr (FP == 8) {
            float4 v0 = ((const float4*)xr)[lane * 2];
            float4 v1 = ((const float4*)xr)[lane * 2 + 1];
            acc[0] += wh * v0.x; acc[1] += wh * v0.y;
            acc[2] += wh * v0.z; acc[3] += wh * v0.w;
            acc[4] += wh * v1.x; acc[5] += wh * v1.y;
            acc[6] += wh * v1.z; acc[7] += wh * v1.w;
        } else {
            float2 v = ((const float2*)xr)[lane];
            acc[0] += wh * v.x; acc[1] += wh * v.y;
        }
    }
    float denom;
    if constexpr (H == 4)
        denom = (myh == 0) ? ssum[0] : (myh == 1) ? ssum[1] : (myh == 2) ? ssum[2] : ssum[3];
    else
        denom = ssum[0];
    float inv = 1.f / denom;
#pragma unroll
    for (int q = 0; q < FP; q++) {
        int f = lane * FP + q;
        float v = acc[q] * inv + bias[f];
        v = v > 0.f ? v : expm1f(v);   // elu applied after every GAT layer
        out[(size_t)i * F + f] = v;
    }
}

// ---------------- global mean pool + output projection ---------------------
__global__ void pool_kernel(const float* __restrict__ h) {
    __shared__ float sacc[64];
    int t = threadIdx.x;
    if (t < 64) sacc[t] = 0.f;
    __syncthreads();
    int col = t & 63;
    int rpb = blockDim.x >> 6;  // rows per block pass
    float a = 0.f;
    for (int r = blockIdx.x * rpb + (t >> 6); r < N_NODES; r += gridDim.x * rpb)
        a += h[(size_t)r * 64 + col];
    atomicAdd(&sacc[col], a);
    __syncthreads();
    if (t < 64) atomicAdd(&g_pool[t], sacc[t]);
}

__global__ void final_kernel(const float* __restrict__ w_out,
                             const float* __restrict__ b_out,
                             float* __restrict__ out) {
    int j = threadIdx.x;  // 0..127
    float s = b_out[j];
    const float invn = 1.f / (float)N_NODES;
    for (int k = 0; k < 64; k++)
        s += g_pool[k] * invn * w_out[k * 128 + j];
    out[j] = s;
}

// ---------------- launcher -------------------------------------------------
extern "C" void kernel_launch(void* const* d_in, const int* in_sizes, int n_in,
                              void* d_out, int out_size) {
    const float* x     = (const float*)d_in[0];
    const int*   ei    = (const int*)d_in[1];
    const int*   src   = ei;
    const int*   dst   = ei + N_EDGES;
    const float* w_in  = (const float*)d_in[2];
    const float* b_in  = (const float*)d_in[3];
    const float* W0    = (const float*)d_in[4];
    const float* as0   = (const float*)d_in[5];
    const float* ad0   = (const float*)d_in[6];
    const float* bb0   = (const float*)d_in[7];
    const float* W1    = (const float*)d_in[8];
    const float* as1   = (const float*)d_in[9];
    const float* ad1   = (const float*)d_in[10];
    const float* bb1   = (const float*)d_in[11];
    const float* W2    = (const float*)d_in[12];
    const float* as2   = (const float*)d_in[13];
    const float* ad2   = (const float*)d_in[14];
    const float* bb2   = (const float*)d_in[15];
    const float* w_out = (const float*)d_in[16];
    const float* b_out = (const float*)d_in[17];
    float* out = (float*)d_out;

    void *p_h64, *p_xf, *p_hA, *p_hB;
    cudaGetSymbolAddress(&p_h64, g_h64);
    cudaGetSymbolAddress(&p_xf,  g_xf);
    cudaGetSymbolAddress(&p_hA,  g_hA);
    cudaGetSymbolAddress(&p_hB,  g_hB);
    float* h64 = (float*)p_h64;
    float* xf  = (float*)p_xf;
    float* hA  = (float*)p_hA;
    float* hB  = (float*)p_hB;

    const int EB = (N_EDGES + 255) / 256;
    const int NB = (N_NODES + 255) / 256;
    const int MY = (N_NODES + 127) / 128;   // 391 row-blocks of 128
    const int WARPB = N_NODES / 8;          // 6250 blocks of 8 warps

    // CSR build (per-launch; deterministic workload)
    zero_kernel<<<NB, 256>>>();
    hist_kernel<<<EB, 256>>>(dst);
    scan_kernel<<<1, 1024>>>();
    scatter_kernel<<<EB, 256>>>(src, dst);

    // input MLP: h64 = elu(x @ w_in + b_in)
    sgemm_kernel<<<dim3(1, MY), 256>>>(x, w_in, b_in, h64, N_NODES, 64, 256, 1);

    // GAT layer 0 (H=4, D=64, concat)
    sgemm_kernel<<<dim3(4, MY), 256>>>(h64, W0, nullptr, xf, N_NODES, 256, 64, 0);
    compute_e_kernel<4, 64><<<WARPB, 256>>>(xf, as0, ad0);
    gat_agg_kernel<4, 64><<<WARPB, 256>>>(xf, bb0, hA);

    // GAT layer 1 (H=4, D=64, concat)
    sgemm_kernel<<<dim3(4, MY), 256>>>(hA, W1, nullptr, xf, N_NODES, 256, 256, 0);
    compute_e_kernel<4, 64><<<WARPB, 256>>>(xf, as1, ad1);
    gat_agg_kernel<4, 64><<<WARPB, 256>>>(xf, bb1, hB);

    // GAT layer 2 (H=1, D=64, mean over heads == identity)
    sgemm_kernel<<<dim3(1, MY), 256>>>(hB, W2, nullptr, xf, N_NODES, 64, 256, 0);
    compute_e_kernel<1, 64><<<WARPB, 256>>>(xf, as2, ad2);
    gat_agg_kernel<1, 64><<<WARPB, 256>>>(xf, bb2, h64);

    // global mean pool + out projection
    pool_kernel<<<256, 256>>>(h64);
    final_kernel<<<1, 128>>>(w_out, b_out, out);
}

// round 3
// speedup vs baseline: 1.3654x; 1.1314x over previous
#include <cuda_runtime.h>
#include <math.h>
#include <stdint.h>

#define N_NODES 50000
#define N_EDGES 800000

// ---------------- scratch (static device globals; no runtime alloc) --------
__device__ int   g_counts[N_NODES];
__device__ int   g_offsets[N_NODES + 1];
__device__ int   g_cursor[N_NODES];
__device__ int   g_csr[N_EDGES];
__device__ float g_h64[(size_t)N_NODES * 64];
__device__ float g_xf [(size_t)N_NODES * 256];
__device__ float g_hA [(size_t)N_NODES * 256];
__device__ float g_hB [(size_t)N_NODES * 256];
__device__ float g_esrc[N_NODES * 4];
__device__ float g_edst[N_NODES * 4];
__device__ float g_pool[64];

// ---------------- CSR build ------------------------------------------------
__global__ void zero_kernel() {
    int i = blockIdx.x * blockDim.x + threadIdx.x;
    if (i < N_NODES) g_counts[i] = 0;
    if (i < 64) g_pool[i] = 0.f;
}

__global__ void hist_kernel(const int* __restrict__ dst) {
    int i = blockIdx.x * blockDim.x + threadIdx.x;
    if (i < N_EDGES) atomicAdd(&g_counts[dst[i]], 1);
}

__global__ void scan_kernel() {
    __shared__ int ssum[1024];
    int t = threadIdx.x;
    const int CH = (N_NODES + 1023) / 1024;
    int base = t * CH;
    int s = 0;
    for (int c = 0; c < CH; c++) {
        int idx = base + c;
        if (idx < N_NODES) s += g_counts[idx];
    }
    ssum[t] = s;
    __syncthreads();
    for (int off = 1; off < 1024; off <<= 1) {
        int v = (t >= off) ? ssum[t - off] : 0;
        __syncthreads();
        ssum[t] += v;
        __syncthreads();
    }
    int run = (t == 0) ? 0 : ssum[t - 1];
    for (int c = 0; c < CH; c++) {
        int idx = base + c;
        if (idx < N_NODES) {
            g_offsets[idx] = run;
            g_cursor[idx]  = run;
            run += g_counts[idx];
        }
    }
    if (t == 1023) g_offsets[N_NODES] = ssum[1023];
}

__global__ void scatter_kernel(const int* __restrict__ src, const int* __restrict__ dst) {
    int i = blockIdx.x * blockDim.x + threadIdx.x;
    if (i < N_EDGES) {
        int p = atomicAdd(&g_cursor[dst[i]], 1);
        g_csr[p] = src[i];
    }
}

// ---------------- TF32 tensor-core GEMM ------------------------------------
// C[MxN] = A[MxK] * B[KxN], row-major. mode 0: plain; mode 1: +bias, elu.
// 128x64 block tile, 8 warps (4x2), warp computes 32x32 via m16n8k8 mma.
__device__ __forceinline__ float tf32r(float x) {
    float y;
    asm("cvt.rna.tf32.f32 %0, %1;" : "=f"(y) : "f"(x));
    return y;
}

__device__ __forceinline__ void mma_tf32(float* c, const uint32_t* a, uint32_t b0, uint32_t b1) {
    asm volatile(
        "mma.sync.aligned.m16n8k8.row.col.f32.tf32.tf32.f32 "
        "{%0,%1,%2,%3},{%4,%5,%6,%7},{%8,%9},{%0,%1,%2,%3};"
        : "+f"(c[0]), "+f"(c[1]), "+f"(c[2]), "+f"(c[3])
        : "r"(a[0]), "r"(a[1]), "r"(a[2]), "r"(a[3]), "r"(b0), "r"(b1));
}

__global__ __launch_bounds__(256) void tf32gemm_kernel(
        const float* __restrict__ A, const float* __restrict__ B,
        const float* __restrict__ bias, float* __restrict__ C,
        int M, int N, int K, int mode) {
    const int BM = 128, BN = 64, BK = 32;
    __shared__ float As[BK][BM + 4];   // [k][m]
    __shared__ float Bs[BK][BN + 4];   // [k][n]
    int tx = threadIdx.x;
    int bm = blockIdx.y * BM;
    int bn = blockIdx.x * BN;
    int wid = tx >> 5, lane = tx & 31;
    int wm = (wid >> 1) * 32;          // warp m offset within block
    int wn = (wid & 1) * 32;           // warp n offset within block
    const int gid = lane >> 2;         // group id 0..7
    const int tig = lane & 3;          // thread in group 0..3

    float acc[2][4][4];
#pragma unroll
    for (int mt = 0; mt < 2; mt++)
#pragma unroll
        for (int nt = 0; nt < 4; nt++)
#pragma unroll
            for (int q = 0; q < 4; q++) acc[mt][nt][q] = 0.f;

    const float4 z4 = make_float4(0.f, 0.f, 0.f, 0.f);
    float4 pa[4], pb[2];

    // prefetch tile 0
#pragma unroll
    for (int q = 0; q < 4; q++) {
        int idx = tx + q * 256;
        int row = idx >> 3;
        int kq  = (idx & 7) * 4;
        int gm  = bm + row;
        pa[q] = (gm < M) ? *(const float4*)&A[(size_t)gm * K + kq] : z4;
    }
#pragma unroll
    for (int q = 0; q < 2; q++) {
        int idx = tx + q * 256;
        int row = idx >> 4;
        int col = (idx & 15) * 4;
        pb[q] = *(const float4*)&B[(size_t)row * N + bn + col];
    }

    for (int k0 = 0; k0 < K; k0 += BK) {
        // commit prefetched tile (tf32-rounded) into smem
#pragma unroll
        for (int q = 0; q < 4; q++) {
            int idx = tx + q * 256;
            int row = idx >> 3;
            int kq  = (idx & 7) * 4;
            As[kq + 0][row] = tf32r(pa[q].x);
            As[kq + 1][row] = tf32r(pa[q].y);
            As[kq + 2][row] = tf32r(pa[q].z);
            As[kq + 3][row] = tf32r(pa[q].w);
        }
#pragma unroll
        for (int q = 0; q < 2; q++) {
            int idx = tx + q * 256;
            int row = idx >> 4;
            int col = (idx & 15) * 4;
            Bs[row][col + 0] = tf32r(pb[q].x);
            Bs[row][col + 1] = tf32r(pb[q].y);
            Bs[row][col + 2] = tf32r(pb[q].z);
            Bs[row][col + 3] = tf32r(pb[q].w);
        }
        __syncthreads();

        // prefetch next tile
        if (k0 + BK < K) {
            int kk = k0 + BK;
#pragma unroll
            for (int q = 0; q < 4; q++) {
                int idx = tx + q * 256;
                int row = idx >> 3;
                int kq  = (idx & 7) * 4;
                int gm  = bm + row;
                pa[q] = (gm < M) ? *(const float4*)&A[(size_t)gm * K + kk + kq] : z4;
            }
#pragma unroll
            for (int q = 0; q < 2; q++) {
                int idx = tx + q * 256;
                int row = idx >> 4;
                int col = (idx & 15) * 4;
                pb[q] = *(const float4*)&B[(size_t)(kk + row) * N + bn + col];
            }
        }

        // 4 k-steps of 8
#pragma unroll
        for (int ks = 0; ks < 4; ks++) {
            int kb = ks * 8;
            uint32_t af[2][4];
#pragma unroll
            for (int mt = 0; mt < 2; mt++) {
                int r = wm + mt * 16 + gid;
                af[mt][0] = __float_as_uint(As[kb + tig][r]);
                af[mt][1] = __float_as_uint(As[kb + tig][r + 8]);
                af[mt][2] = __float_as_uint(As[kb + tig + 4][r]);
                af[mt][3] = __float_as_uint(As[kb + tig + 4][r + 8]);
            }
#pragma unroll
            for (int nt = 0; nt < 4; nt++) {
                int c = wn + nt * 8 + gid;
                uint32_t b0 = __float_as_uint(Bs[kb + tig][c]);
                uint32_t b1 = __float_as_uint(Bs[kb + tig + 4][c]);
                mma_tf32(acc[0][nt], af[0], b0, b1);
                mma_tf32(acc[1][nt], af[1], b0, b1);
            }
        }
        __syncthreads();
    }

    // epilogue
#pragma unroll
    for (int mt = 0; mt < 2; mt++) {
#pragma unroll
        for (int half = 0; half < 2; half++) {
            int m = bm + wm + mt * 16 + gid + half * 8;
            if (m >= M) continue;
#pragma unroll
            for (int nt = 0; nt < 4; nt++) {
                int n = bn + wn + nt * 8 + 2 * tig;
                float v0 = acc[mt][nt][half * 2 + 0];
                float v1 = acc[mt][nt][half * 2 + 1];
                if (mode == 1) {
                    v0 += bias[n];
                    v1 += bias[n + 1];
                    v0 = v0 > 0.f ? v0 : expm1f(v0);
                    v1 = v1 > 0.f ? v1 : expm1f(v1);
                }
                *(float2*)&C[(size_t)m * N + n] = make_float2(v0, v1);
            }
        }
    }
}

// ---------------- attention logits: e_src / e_dst --------------------------
template <int H, int D>
__global__ void compute_e_kernel(const float* __restrict__ xf,
                                 const float* __restrict__ a_s,
                                 const float* __restrict__ a_d) {
    constexpr int F = H * D;
    constexpr int FP = F / 32;
    int gw = (blockIdx.x * blockDim.x + threadIdx.x) >> 5;
    int lane = threadIdx.x & 31;
    if (gw >= N_NODES) return;
    const float* xr = xf + (size_t)gw * F;
    float ps = 0.f, pd = 0.f;
#pragma unroll
    for (int q = 0; q < FP; q++) {
        int f = lane * FP + q;
        float v = xr[f];
        ps += v * a_s[f];
        pd += v * a_d[f];
    }
    constexpr int G = 32 / H;  // lanes per head
#pragma unroll
    for (int off = G >> 1; off; off >>= 1) {
        ps += __shfl_down_sync(0xffffffffu, ps, off);
        pd += __shfl_down_sync(0xffffffffu, pd, off);
    }
    if ((lane & (G - 1)) == 0) {
        int h = lane / G;
        g_esrc[gw * H + h] = ps;
        g_edst[gw * H + h] = pd;
    }
}

// ---------------- GAT aggregation: warp per destination node ---------------
template <int H, int D>
__global__ void gat_agg_kernel(const float* __restrict__ xf,
                               const float* __restrict__ bias,
                               float* __restrict__ out) {
    constexpr int F = H * D;
    constexpr int FP = F / 32;
    int gw = (blockIdx.x * blockDim.x + threadIdx.x) >> 5;
    int lane = threadIdx.x & 31;
    if (gw >= N_NODES) return;
    const int i = gw;
    const int beg = g_offsets[i], end = g_offsets[i + 1];

    float edst_i[H], eself[H], m[H];
#pragma unroll
    for (int h = 0; h < H; h++) {
        edst_i[h] = g_edst[i * H + h];
        float v = g_esrc[i * H + h] + edst_i[h];
        v = v > 0.f ? v : 0.2f * v;
        eself[h] = v;
        m[h] = v;  // self-loop participates in max
    }
    // pass 1: segment max over incoming edges (scalar logits only)
    for (int k = beg + lane; k < end; k += 32) {
        int s = g_csr[k];
#pragma unroll
        for (int h = 0; h < H; h++) {
            float v = g_esrc[s * H + h] + edst_i[h];
            v = v > 0.f ? v : 0.2f * v;
            m[h] = fmaxf(m[h], v);
        }
    }
#pragma unroll
    for (int h = 0; h < H; h++)
#pragma unroll
        for (int off = 16; off; off >>= 1)
            m[h] = fmaxf(m[h], __shfl_xor_sync(0xffffffffu, m[h], off));

    // pass 2: exp-weights, running sum, warp-cooperative feature gather
    float acc[FP];
#pragma unroll
    for (int q = 0; q < FP; q++) acc[q] = 0.f;
    float ssum[H];
#pragma unroll
    for (int h = 0; h < H; h++) ssum[h] = 0.f;
    const int myh = (lane * FP) / D;

    for (int base = beg; base < end; base += 32) {
        int k = base + lane;
        int cnt = min(32, end - base);
        int s = 0;
        float w[H];
#pragma unroll
        for (int h = 0; h < H; h++) w[h] = 0.f;
        if (k < end) {
            s = g_csr[k];
#pragma unroll
            for (int h = 0; h < H; h++) {
                float v = g_esrc[s * H + h] + edst_i[h];
                v = v > 0.f ? v : 0.2f * v;
                float ww = __expf(v - m[h]);
                w[h] = ww;
                ssum[h] += ww;
            }
        }
        for (int j = 0; j < cnt; j++) {
            int sj = __shfl_sync(0xffffffffu, s, j);
            float wh;
            if constexpr (H == 4) {
                float w0 = __shfl_sync(0xffffffffu, w[0], j);
                float w1 = __shfl_sync(0xffffffffu, w[1], j);
                float w2 = __shfl_sync(0xffffffffu, w[2], j);
                float w3 = __shfl_sync(0xffffffffu, w[3], j);
                wh = (myh == 0) ? w0 : (myh == 1) ? w1 : (myh == 2) ? w2 : w3;
            } else {
                wh = __shfl_sync(0xffffffffu, w[0], j);
            }
            const float* xr = xf + (size_t)sj * F;
            if constexpr (FP == 8) {
                float4 v0 = ((const float4*)xr)[lane * 2];
                float4 v1 = ((const float4*)xr)[lane * 2 + 1];
                acc[0] += wh * v0.x; acc[1] += wh * v0.y;
                acc[2] += wh * v0.z; acc[3] += wh * v0.w;
                acc[4] += wh * v1.x; acc[5] += wh * v1.y;
                acc[6] += wh * v1.z; acc[7] += wh * v1.w;
            } else {
                float2 v = ((const float2*)xr)[lane];
                acc[0] += wh * v.x; acc[1] += wh * v.y;
            }
        }
    }
    // total exp-sum across the warp, then fold in self-loop (uniform on all lanes)
#pragma unroll
    for (int h = 0; h < H; h++)
#pragma unroll
        for (int off = 16; off; off >>= 1)
            ssum[h] += __shfl_xor_sync(0xffffffffu, ssum[h], off);
    float wself[H];
#pragma unroll
    for (int h = 0; h < H; h++) {
        wself[h] = __expf(eself[h] - m[h]);
        ssum[h] += wself[h];
    }
    {
        float wh;
        if constexpr (H == 4)
            wh = (myh == 0) ? wself[0] : (myh == 1) ? wself[1] : (myh == 2) ? wself[2] : wself[3];
        else
            wh = wself[0];
        const float* xr = xf + (size_t)i * F;
        if constexpr (FP == 8) {
            float4 v0 = ((const float4*)xr)[lane * 2];
            float4 v1 = ((const float4*)xr)[lane * 2 + 1];
            acc[0] += wh * v0.x; acc[1] += wh * v0.y;
            acc[2] += wh * v0.z; acc[3] += wh * v0.w;
            acc[4] += wh * v1.x; acc[5] += wh * v1.y;
            acc[6] += wh * v1.z; acc[7] += wh * v1.w;
        } else {
            float2 v = ((const float2*)xr)[lane];
            acc[0] += wh * v.x; acc[1] += wh * v.y;
        }
    }
    float denom;
    if constexpr (H == 4)
        denom = (myh == 0) ? ssum[0] : (myh == 1) ? ssum[1] : (myh == 2) ? ssum[2] : ssum[3];
    else
        denom = ssum[0];
    float inv = 1.f / denom;
#pragma unroll
    for (int q = 0; q < FP; q++) {
        int f = lane * FP + q;
        float v = acc[q] * inv + bias[f];
        v = v > 0.f ? v : expm1f(v);   // elu applied after every GAT layer
        out[(size_t)i * F + f] = v;
    }
}

// ---------------- global mean pool + output projection ---------------------
__global__ void pool_kernel(const float* __restrict__ h) {
    __shared__ float sacc[64];
    int t = threadIdx.x;
    if (t < 64) sacc[t] = 0.f;
    __syncthreads();
    int col = t & 63;
    int rpb = blockDim.x >> 6;  // rows per block pass
    float a = 0.f;
    for (int r = blockIdx.x * rpb + (t >> 6); r < N_NODES; r += gridDim.x * rpb)
        a += h[(size_t)r * 64 + col];
    atomicAdd(&sacc[col], a);
    __syncthreads();
    if (t < 64) atomicAdd(&g_pool[t], sacc[t]);
}

__global__ void final_kernel(const float* __restrict__ w_out,
                             const float* __restrict__ b_out,
                             float* __restrict__ out) {
    int j = threadIdx.x;  // 0..127
    float s = b_out[j];
    const float invn = 1.f / (float)N_NODES;
    for (int k = 0; k < 64; k++)
        s += g_pool[k] * invn * w_out[k * 128 + j];
    out[j] = s;
}

// ---------------- launcher -------------------------------------------------
extern "C" void kernel_launch(void* const* d_in, const int* in_sizes, int n_in,
                              void* d_out, int out_size) {
    const float* x     = (const float*)d_in[0];
    const int*   ei    = (const int*)d_in[1];
    const int*   src   = ei;
    const int*   dst   = ei + N_EDGES;
    const float* w_in  = (const float*)d_in[2];
    const float* b_in  = (const float*)d_in[3];
    const float* W0    = (const float*)d_in[4];
    const float* as0   = (const float*)d_in[5];
    const float* ad0   = (const float*)d_in[6];
    const float* bb0   = (const float*)d_in[7];
    const float* W1    = (const float*)d_in[8];
    const float* as1   = (const float*)d_in[9];
    const float* ad1   = (const float*)d_in[10];
    const float* bb1   = (const float*)d_in[11];
    const float* W2    = (const float*)d_in[12];
    const float* as2   = (const float*)d_in[13];
    const float* ad2   = (const float*)d_in[14];
    const float* bb2   = (const float*)d_in[15];
    const float* w_out = (const float*)d_in[16];
    const float* b_out = (const float*)d_in[17];
    float* out = (float*)d_out;

    void *p_h64, *p_xf, *p_hA, *p_hB;
    cudaGetSymbolAddress(&p_h64, g_h64);
    cudaGetSymbolAddress(&p_xf,  g_xf);
    cudaGetSymbolAddress(&p_hA,  g_hA);
    cudaGetSymbolAddress(&p_hB,  g_hB);
    float* h64 = (float*)p_h64;
    float* xf  = (float*)p_xf;
    float* hA  = (float*)p_hA;
    float* hB  = (float*)p_hB;

    const int EB = (N_EDGES + 255) / 256;
    const int NB = (N_NODES + 255) / 256;
    const int MY = (N_NODES + 127) / 128;   // 391 row-blocks of 128
    const int WARPB = N_NODES / 8;          // 6250 blocks of 8 warps

    // CSR build (per-launch; deterministic workload)
    zero_kernel<<<NB, 256>>>();
    hist_kernel<<<EB, 256>>>(dst);
    scan_kernel<<<1, 1024>>>();
    scatter_kernel<<<EB, 256>>>(src, dst);

    // input MLP: h64 = elu(x @ w_in + b_in)
    tf32gemm_kernel<<<dim3(1, MY), 256>>>(x, w_in, b_in, h64, N_NODES, 64, 256, 1);

    // GAT layer 0 (H=4, D=64, concat)
    tf32gemm_kernel<<<dim3(4, MY), 256>>>(h64, W0, nullptr, xf, N_NODES, 256, 64, 0);
    compute_e_kernel<4, 64><<<WARPB, 256>>>(xf, as0, ad0);
    gat_agg_kernel<4, 64><<<WARPB, 256>>>(xf, bb0, hA);

    // GAT layer 1 (H=4, D=64, concat)
    tf32gemm_kernel<<<dim3(4, MY), 256>>>(hA, W1, nullptr, xf, N_NODES, 256, 256, 0);
    compute_e_kernel<4, 64><<<WARPB, 256>>>(xf, as1, ad1);
    gat_agg_kernel<4, 64><<<WARPB, 256>>>(xf, bb1, hB);

    // GAT layer 2 (H=1, D=64, mean over heads == identity)
    tf32gemm_kernel<<<dim3(1, MY), 256>>>(hB, W2, nullptr, xf, N_NODES, 64, 256, 0);
    compute_e_kernel<1, 64><<<WARPB, 256>>>(xf, as2, ad2);
    gat_agg_kernel<1, 64><<<WARPB, 256>>>(xf, bb2, h64);

    // global mean pool + out projection
    pool_kernel<<<256, 256>>>(h64);
    final_kernel<<<1, 128>>>(w_out, b_out, out);
}